// round 10
// baseline (speedup 1.0000x reference)
#include <cuda_runtime.h>
#include <cuda_fp16.h>
#include <math.h>
#include <stdint.h>

// ---------------- problem constants ----------------
#define B_      32
#define HW_     56
#define L_      3136
#define C_      384
#define NH_     12
#define HD_     32
#define WS_     7
#define NTOK_   49
#define NWIN_   64
#define BN_     2048
#define MTOT_   100352
#define HID_    1536
#define QKVN_   1152
#define SHIFT_  3
#define SCALE_  0.17677669529663687f

// ---------------- scratch ----------------
__device__ __half g_win[(size_t)MTOT_ * C_];
__device__ __half g_qkv[(size_t)MTOT_ * QKVN_];
__device__ __half g_att[(size_t)MTOT_ * C_];
__device__ float  g_x1 [(size_t)MTOT_ * C_];
__device__ __half g_h2 [(size_t)MTOT_ * C_];
__device__ __half g_hid[(size_t)MTOT_ * HID_];
__device__ __half g_wh_qkv[(size_t)QKVN_ * C_];
__device__ __half g_wh_proj[(size_t)C_ * C_];
__device__ __half g_wh_fc1[(size_t)HID_ * C_];
__device__ __half g_wh_fc2[(size_t)C_ * HID_];

// ---------------- helpers ----------------
__device__ __forceinline__ void cp_async16(uint32_t saddr, const void* gptr) {
    asm volatile("cp.async.cg.shared.global [%0], [%1], 16;" :: "r"(saddr), "l"(gptr));
}
#define CP_COMMIT() asm volatile("cp.async.commit_group;" ::: "memory")
#define CP_WAIT(n)  asm volatile("cp.async.wait_group %0;" :: "n"(n) : "memory")

__device__ __forceinline__ void mma16816(float* c, const uint32_t* a, const uint32_t* b) {
    asm volatile("mma.sync.aligned.m16n8k16.row.col.f32.f16.f16.f32 "
        "{%0,%1,%2,%3}, {%4,%5,%6,%7}, {%8,%9}, {%0,%1,%2,%3};"
        : "+f"(c[0]), "+f"(c[1]), "+f"(c[2]), "+f"(c[3])
        : "r"(a[0]), "r"(a[1]), "r"(a[2]), "r"(a[3]), "r"(b[0]), "r"(b[1]));
}

// ---------------- row map ----------------
__device__ __forceinline__ int win_row_to_orig(int r) {
    int bn = r / NTOK_, n = r - bn * NTOK_;
    int b  = bn >> 6,  wi = bn & 63;
    int i = n / WS_, j = n - i * WS_;
    int h = (wi >> 3) * WS_ + i + SHIFT_; if (h >= HW_) h -= HW_;
    int w = (wi & 7)  * WS_ + j + SHIFT_; if (w >= HW_) w -= HW_;
    return b * L_ + h * HW_ + w;
}

// ---------------- LayerNorm (half output, shifted window order) ----------------
__global__ __launch_bounds__(128) void ln_kernel(const float* __restrict__ x,
                                                 const float* __restrict__ g,
                                                 const float* __restrict__ b,
                                                 __half* __restrict__ out)
{
    int r = blockIdx.x;
    int src_row = win_row_to_orig(r);
    const float* src = x + (size_t)src_row * C_;
    int t = threadIdx.x;
    float v[3], s = 0.f, s2 = 0.f;
#pragma unroll
    for (int l = 0; l < 3; ++l) { v[l] = src[t + l * 128]; s += v[l]; s2 += v[l] * v[l]; }
    __shared__ float red[8];
#pragma unroll
    for (int o = 16; o > 0; o >>= 1) {
        s  += __shfl_down_sync(0xffffffffu, s,  o);
        s2 += __shfl_down_sync(0xffffffffu, s2, o);
    }
    int lane = t & 31, wid = t >> 5;
    if (lane == 0) { red[wid] = s; red[4 + wid] = s2; }
    __syncthreads();
    s  = red[0] + red[1] + red[2] + red[3];
    s2 = red[4] + red[5] + red[6] + red[7];
    float mean = s * (1.f / C_);
    float var  = s2 * (1.f / C_) - mean * mean;
    float inv  = rsqrtf(var + 1e-5f);
    __half* dst = out + (size_t)r * C_;
#pragma unroll
    for (int l = 0; l < 3; ++l) {
        int c = t + l * 128;
        dst[c] = __float2half((v[l] - mean) * inv * g[c] + b[c]);
    }
}

// ---------------- weight transpose+convert ----------------
__global__ __launch_bounds__(256) void transpose_half(const float* __restrict__ src,
                                                      __half* __restrict__ dst,
                                                      int K, int N)
{
    __shared__ float t[32][33];
    int bx = blockIdx.x * 32, by = blockIdx.y * 32;
    int tx = threadIdx.x & 31, ty = threadIdx.x >> 5;
#pragma unroll
    for (int i = 0; i < 4; ++i)
        t[ty + i * 8][tx] = src[(size_t)(by + ty + i * 8) * N + bx + tx];
    __syncthreads();
#pragma unroll
    for (int i = 0; i < 4; ++i)
        dst[(size_t)(bx + ty + i * 8) * K + by + tx] = __float2half(t[tx][ty + i * 8]);
}

// ---------------- generic fp16 mma GEMM (128x128 block, 4-stage ring) ----------------
// EPI: 0=+bias->half ; 1=+bias,gelu->half ; 3=+bias+residual->float
#define ASTR 40
#define ABYT (128 * ASTR * 2)
#define STGB (2 * ABYT)
#define NSTG 4
#define MM_SMEM (NSTG * STGB)

template<int EPI>
__global__ __launch_bounds__(256, 2) void mm_kernel(const __half* __restrict__ A,
                                                    const __half* __restrict__ Wt,
                                                    const float* __restrict__ bias,
                                                    const float* __restrict__ Res,
                                                    void* __restrict__ OutV,
                                                    int K, int N)
{
    extern __shared__ __half sm[];
    const int tid = threadIdx.x;
    const int w = tid >> 5, lane = tid & 31;
    const int warpM = w >> 1, warpN = w & 1;
    const int g = lane >> 2, tig = lane & 3;
    const int bx = blockIdx.x, by = blockIdx.y;

    const __half* Ab = A  + (size_t)by * 128 * K;
    const __half* Bb = Wt + (size_t)bx * 128 * K;
    uint32_t s0 = (uint32_t)__cvta_generic_to_shared(sm);

    float acc[2][8][4];
#pragma unroll
    for (int mt = 0; mt < 2; ++mt)
#pragma unroll
        for (int nt = 0; nt < 8; ++nt)
#pragma unroll
            for (int i = 0; i < 4; ++i) acc[mt][nt][i] = 0.f;

    const int KT = K >> 5;
    const int ca0 = tid, ca1 = tid + 256;

#define LOAD_STAGE(kt, st) do {                                                     \
        int _k0 = (kt) << 5;                                                        \
        uint32_t _ab = s0 + (st) * STGB;                                            \
        uint32_t _bb = _ab + ABYT;                                                  \
        { int r = ca0 >> 2, sg = ca0 & 3;                                           \
          cp_async16(_ab + (r * ASTR + sg * 8) * 2, Ab + (size_t)r * K + _k0 + sg * 8); } \
        { int r = ca1 >> 2, sg = ca1 & 3;                                           \
          cp_async16(_ab + (r * ASTR + sg * 8) * 2, Ab + (size_t)r * K + _k0 + sg * 8); } \
        { int r = ca0 >> 2, sg = ca0 & 3;                                           \
          cp_async16(_bb + (r * ASTR + sg * 8) * 2, Bb + (size_t)r * K + _k0 + sg * 8); } \
        { int r = ca1 >> 2, sg = ca1 & 3;                                           \
          cp_async16(_bb + (r * ASTR + sg * 8) * 2, Bb + (size_t)r * K + _k0 + sg * 8); } \
        CP_COMMIT();                                                                \
    } while (0)

    LOAD_STAGE(0, 0);
    LOAD_STAGE(1, 1);

    for (int kt = 0; kt < KT; ++kt) {
        int st = kt & 3;
        if (kt + 2 < KT)      { LOAD_STAGE(kt + 2, (kt + 2) & 3); CP_WAIT(2); }
        else if (kt + 1 < KT) { CP_WAIT(1); }
        else                  { CP_WAIT(0); }
        __syncthreads();

        const uint32_t* Au = (const uint32_t*)(sm + st * (STGB / 2));
        const uint32_t* Bu = Au + ABYT / 4;
#pragma unroll
        for (int s = 0; s < 2; ++s) {
            uint32_t af[2][4], bf[8][2];
            int c2 = s * 8 + tig;
#pragma unroll
            for (int mt = 0; mt < 2; ++mt) {
                int r = warpM * 32 + mt * 16 + g;
                af[mt][0] = Au[r * 20 + c2];
                af[mt][1] = Au[(r + 8) * 20 + c2];
                af[mt][2] = Au[r * 20 + c2 + 4];
                af[mt][3] = Au[(r + 8) * 20 + c2 + 4];
            }
#pragma unroll
            for (int nt = 0; nt < 8; ++nt) {
                int n = warpN * 64 + nt * 8 + g;
                bf[nt][0] = Bu[n * 20 + c2];
                bf[nt][1] = Bu[n * 20 + c2 + 4];
            }
#pragma unroll
            for (int mt = 0; mt < 2; ++mt)
#pragma unroll
                for (int nt = 0; nt < 8; ++nt)
                    mma16816(acc[mt][nt], af[mt], bf[nt]);
        }
    }

#pragma unroll
    for (int mt = 0; mt < 2; ++mt) {
#pragma unroll
        for (int rr = 0; rr < 2; ++rr) {
            int row = by * 128 + warpM * 32 + mt * 16 + g + rr * 8;
            if (EPI == 3) {
                float* dst = (float*)OutV + (size_t)row * N;
#pragma unroll
                for (int nt = 0; nt < 8; ++nt) {
                    int c = bx * 128 + warpN * 64 + nt * 8 + tig * 2;
                    dst[c]     = acc[mt][nt][rr * 2]     + bias[c]     + Res[(size_t)row * N + c];
                    dst[c + 1] = acc[mt][nt][rr * 2 + 1] + bias[c + 1] + Res[(size_t)row * N + c + 1];
                }
            } else {
                __half* dst = (__half*)OutV + (size_t)row * N;
#pragma unroll
                for (int nt = 0; nt < 8; ++nt) {
                    int c = bx * 128 + warpN * 64 + nt * 8 + tig * 2;
                    float v0 = acc[mt][nt][rr * 2]     + bias[c];
                    float v1 = acc[mt][nt][rr * 2 + 1] + bias[c + 1];
                    if (EPI == 1) {
                        v0 = 0.5f * v0 * (1.f + erff(v0 * 0.70710678118654752f));
                        v1 = 0.5f * v1 * (1.f + erff(v1 * 0.70710678118654752f));
                    }
                    *(__half2*)(dst + c) = __halves2half2(__float2half(v0), __float2half(v1));
                }
            }
        }
    }
}

// ---------------- fused proj + window-reverse + residual + LN2 ----------------
// block = 64 rows x full N=384; 8 warps (2x4), warp tile 32x96
#define A2R  64
#define STG2 ((A2R + C_) * ASTR * 2)         // 35840 B per stage
#define MM2_SMEM (4 * STG2 + 1024)

__global__ __launch_bounds__(256) void mm2ln_kernel(const __half* __restrict__ A,
                                                    const __half* __restrict__ Wt,
                                                    const float* __restrict__ pbias,
                                                    const float* __restrict__ x,
                                                    const float* __restrict__ n2g,
                                                    const float* __restrict__ n2b,
                                                    float* __restrict__ x1,
                                                    __half* __restrict__ h2)
{
    extern __shared__ __half sm[];
    const int tid = threadIdx.x;
    const int w = tid >> 5, lane = tid & 31;
    const int warpM = w >> 2, warpN = w & 3;
    const int g = lane >> 2, tig = lane & 3;
    const int by = blockIdx.x;

    const __half* Ab = A + (size_t)by * A2R * C_;
    uint32_t s0 = (uint32_t)__cvta_generic_to_shared(sm);
    float* red = (float*)(sm + 4 * (STG2 / 2));   // 64 rows x {sum, sumsq}

    float acc[2][12][4];
#pragma unroll
    for (int mt = 0; mt < 2; ++mt)
#pragma unroll
        for (int nt = 0; nt < 12; ++nt)
#pragma unroll
            for (int i = 0; i < 4; ++i) acc[mt][nt][i] = 0.f;

    const int KT = C_ >> 5;   // 12

#define LOAD_STAGE2(kt, st) do {                                                    \
        int _k0 = (kt) << 5;                                                        \
        uint32_t _sb = s0 + (st) * STG2;                                            \
        _Pragma("unroll")                                                           \
        for (int _i = 0; _i < 7; ++_i) {                                            \
            int c = tid + _i * 256, r = c >> 2, sg = c & 3;                         \
            const __half* src = (r < A2R) ? (Ab + (size_t)r * C_ + _k0 + sg * 8)    \
                                          : (Wt + (size_t)(r - A2R) * C_ + _k0 + sg * 8); \
            cp_async16(_sb + (r * ASTR + sg * 8) * 2, src);                         \
        }                                                                           \
        CP_COMMIT();                                                                \
    } while (0)

    LOAD_STAGE2(0, 0);
    LOAD_STAGE2(1, 1);

    for (int kt = 0; kt < KT; ++kt) {
        int st = kt & 3;
        if (kt + 2 < KT)      { LOAD_STAGE2(kt + 2, (kt + 2) & 3); CP_WAIT(2); }
        else if (kt + 1 < KT) { CP_WAIT(1); }
        else                  { CP_WAIT(0); }
        __syncthreads();

        const uint32_t* Au = (const uint32_t*)(sm + st * (STG2 / 2));
        const uint32_t* Bu = Au + (A2R * ASTR) / 2;
#pragma unroll
        for (int s = 0; s < 2; ++s) {
            uint32_t af[2][4], bf[12][2];
            int c2 = s * 8 + tig;
#pragma unroll
            for (int mt = 0; mt < 2; ++mt) {
                int r = warpM * 32 + mt * 16 + g;
                af[mt][0] = Au[r * 20 + c2];
                af[mt][1] = Au[(r + 8) * 20 + c2];
                af[mt][2] = Au[r * 20 + c2 + 4];
                af[mt][3] = Au[(r + 8) * 20 + c2 + 4];
            }
#pragma unroll
            for (int nt = 0; nt < 12; ++nt) {
                int n = warpN * 96 + nt * 8 + g;
                bf[nt][0] = Bu[n * 20 + c2];
                bf[nt][1] = Bu[n * 20 + c2 + 4];
            }
#pragma unroll
            for (int mt = 0; mt < 2; ++mt)
#pragma unroll
                for (int nt = 0; nt < 12; ++nt)
                    mma16816(acc[mt][nt], af[mt], bf[nt]);
        }
    }

    // ---- epilogue: x1 = x + proj + bias ; LN2 stats; write x1 (fp32) + h2 (half) ----
    if (tid < 128) red[tid] = 0.f;
    __syncthreads();

    int orows[2][2];
#pragma unroll
    for (int mt = 0; mt < 2; ++mt) {
#pragma unroll
        for (int rr = 0; rr < 2; ++rr) {
            int lrow = warpM * 32 + mt * 16 + g + rr * 8;
            int orow = win_row_to_orig(by * A2R + lrow);
            orows[mt][rr] = orow;
            const float* xr = x + (size_t)orow * C_;
            float s = 0.f, s2 = 0.f;
#pragma unroll
            for (int nt = 0; nt < 12; ++nt) {
#pragma unroll
                for (int q = 0; q < 2; ++q) {
                    int c = warpN * 96 + nt * 8 + tig * 2 + q;
                    float v = acc[mt][nt][rr * 2 + q] + pbias[c] + xr[c];
                    acc[mt][nt][rr * 2 + q] = v;
                    s += v; s2 += v * v;
                }
            }
            atomicAdd(&red[lrow * 2],     s);
            atomicAdd(&red[lrow * 2 + 1], s2);
        }
    }
    __syncthreads();

#pragma unroll
    for (int mt = 0; mt < 2; ++mt) {
#pragma unroll
        for (int rr = 0; rr < 2; ++rr) {
            int lrow = warpM * 32 + mt * 16 + g + rr * 8;
            int orow = orows[mt][rr];
            float mean = red[lrow * 2] * (1.f / C_);
            float var  = red[lrow * 2 + 1] * (1.f / C_) - mean * mean;
            float inv  = rsqrtf(var + 1e-5f);
            float*  xd = x1 + (size_t)orow * C_;
            __half* hd = h2 + (size_t)orow * C_;
#pragma unroll
            for (int nt = 0; nt < 12; ++nt) {
                int c = warpN * 96 + nt * 8 + tig * 2;
                float v0 = acc[mt][nt][rr * 2];
                float v1 = acc[mt][nt][rr * 2 + 1];
                *(float2*)(xd + c) = make_float2(v0, v1);
                float h0 = (v0 - mean) * inv * n2g[c]     + n2b[c];
                float h1 = (v1 - mean) * inv * n2g[c + 1] + n2b[c + 1];
                *(__half2*)(hd + c) = __halves2half2(__float2half(h0), __float2half(h1));
            }
        }
    }
}

// ---------------- Attention (half qkv in, half out) ----------------
__global__ __launch_bounds__(128) void attn_kernel(const float* __restrict__ rpb,
                                                   const float* __restrict__ mask)
{
    int bh = blockIdx.x;
    int bn = bh / NH_, head = bh - bn * NH_;
    int t = threadIdx.x;

    __shared__ float q [NTOK_][HD_];
    __shared__ float kk[NTOK_][HD_];
    __shared__ float vv[NTOK_][HD_];
    __shared__ float s [NTOK_][52];

    const __half* base = g_qkv + (size_t)bn * NTOK_ * QKVN_ + head * HD_;
    for (int idx = t; idx < NTOK_ * HD_; idx += 128) {
        int n = idx >> 5, d = idx & 31;
        const __half* p = base + (size_t)n * QKVN_ + d;
        q [n][d] = __half2float(p[0]) * SCALE_;
        kk[n][d] = __half2float(p[C_]);
        vv[n][d] = __half2float(p[2 * C_]);
    }
    __syncthreads();

    int wi = bn & 63;
    const float* mrow = mask + (size_t)wi * NTOK_ * NTOK_;
    for (int idx = t; idx < NTOK_ * NTOK_; idx += 128) {
        int n = idx / NTOK_, m = idx - n * NTOK_;
        float acc = 0.f;
#pragma unroll
        for (int d = 0; d < HD_; ++d) acc = fmaf(q[n][d], kk[m][d], acc);
        int di = n / WS_ - m / WS_ + WS_ - 1;
        int dj = n % WS_ - m % WS_ + WS_ - 1;
        acc += rpb[(di * (2 * WS_ - 1) + dj) * NH_ + head] + mrow[idx];
        s[n][m] = acc;
    }
    __syncthreads();

    if (t < NTOK_) {
        float mx = -1e30f;
#pragma unroll 7
        for (int m = 0; m < NTOK_; ++m) mx = fmaxf(mx, s[t][m]);
        float sum = 0.f;
#pragma unroll 7
        for (int m = 0; m < NTOK_; ++m) { float e = __expf(s[t][m] - mx); s[t][m] = e; sum += e; }
        float inv = 1.f / sum;
#pragma unroll 7
        for (int m = 0; m < NTOK_; ++m) s[t][m] *= inv;
    }
    __syncthreads();

    for (int idx = t; idx < NTOK_ * HD_; idx += 128) {
        int n = idx >> 5, d = idx & 31;
        float acc = 0.f;
#pragma unroll 7
        for (int m = 0; m < NTOK_; ++m) acc = fmaf(s[n][m], vv[m][d], acc);
        g_att[((size_t)bn * NTOK_ + n) * C_ + head * HD_ + d] = __float2half(acc);
    }
}

// ---------------- launch ----------------
extern "C" void kernel_launch(void* const* d_in, const int* in_sizes, int n_in,
                              void* d_out, int out_size)
{
    const float* x       = (const float*)d_in[0];
    const float* mask    = (const float*)d_in[1];
    const float* n1g     = (const float*)d_in[2];
    const float* n1b     = (const float*)d_in[3];
    const float* qkv_w   = (const float*)d_in[4];
    const float* qkv_b   = (const float*)d_in[5];
    const float* rpb     = (const float*)d_in[6];
    const float* proj_w  = (const float*)d_in[7];
    const float* proj_b  = (const float*)d_in[8];
    const float* n2g     = (const float*)d_in[9];
    const float* n2b     = (const float*)d_in[10];
    const float* fc1_w   = (const float*)d_in[11];
    const float* fc1_b   = (const float*)d_in[12];
    const float* fc2_w   = (const float*)d_in[13];
    const float* fc2_b   = (const float*)d_in[14];
    float* out = (float*)d_out;

    __half *p_win, *p_qkv, *p_att, *p_h2, *p_hid;
    float  *p_x1;
    __half *pW_qkv, *pW_proj, *pW_fc1, *pW_fc2;
    cudaGetSymbolAddress((void**)&p_win, g_win);
    cudaGetSymbolAddress((void**)&p_qkv, g_qkv);
    cudaGetSymbolAddress((void**)&p_att, g_att);
    cudaGetSymbolAddress((void**)&p_x1,  g_x1);
    cudaGetSymbolAddress((void**)&p_h2,  g_h2);
    cudaGetSymbolAddress((void**)&p_hid, g_hid);
    cudaGetSymbolAddress((void**)&pW_qkv,  g_wh_qkv);
    cudaGetSymbolAddress((void**)&pW_proj, g_wh_proj);
    cudaGetSymbolAddress((void**)&pW_fc1,  g_wh_fc1);
    cudaGetSymbolAddress((void**)&pW_fc2,  g_wh_fc2);

    cudaFuncSetAttribute(mm_kernel<0>, cudaFuncAttributeMaxDynamicSharedMemorySize, MM_SMEM);
    cudaFuncSetAttribute(mm_kernel<1>, cudaFuncAttributeMaxDynamicSharedMemorySize, MM_SMEM);
    cudaFuncSetAttribute(mm_kernel<3>, cudaFuncAttributeMaxDynamicSharedMemorySize, MM_SMEM);
    cudaFuncSetAttribute(mm2ln_kernel, cudaFuncAttributeMaxDynamicSharedMemorySize, MM2_SMEM);

    // 0) transpose + fp16-convert weights -> [N,K]
    transpose_half<<<dim3(QKVN_ / 32, C_ / 32), 256>>>(qkv_w, pW_qkv, C_, QKVN_);
    transpose_half<<<dim3(C_ / 32, C_ / 32), 256>>>(proj_w, pW_proj, C_, C_);
    transpose_half<<<dim3(HID_ / 32, C_ / 32), 256>>>(fc1_w, pW_fc1, C_, HID_);
    transpose_half<<<dim3(C_ / 32, HID_ / 32), 256>>>(fc2_w, pW_fc2, HID_, C_);

    // 1) LN1 + roll + window partition (half)
    ln_kernel<<<MTOT_, 128>>>(x, n1g, n1b, p_win);

    // 2) QKV GEMM -> half
    mm_kernel<0><<<dim3(QKVN_ / 128, MTOT_ / 128), 256, MM_SMEM>>>(p_win, pW_qkv, qkv_b, nullptr,
                                                                   p_qkv, C_, QKVN_);
    // 3) windowed attention -> half
    attn_kernel<<<BN_ * NH_, 128>>>(rpb, mask);

    // 4) proj + window reverse + residual + LN2 -> x1 (fp32) & h2 (half)
    mm2ln_kernel<<<MTOT_ / A2R, 256, MM2_SMEM>>>(p_att, pW_proj, proj_b, x, n2g, n2b,
                                                 p_x1, p_h2);

    // 5) fc1 + GELU -> half
    mm_kernel<1><<<dim3(HID_ / 128, MTOT_ / 128), 256, MM_SMEM>>>(p_h2, pW_fc1, fc1_b, nullptr,
                                                                  p_hid, C_, HID_);
    // 6) fc2 + residual -> out (float)
    mm_kernel<3><<<dim3(C_ / 128, MTOT_ / 128), 256, MM_SMEM>>>(p_hid, pW_fc2, fc2_b, p_x1,
                                                                out, HID_, C_);
}

// round 13
// speedup vs baseline: 1.0087x; 1.0087x over previous
#include <cuda_runtime.h>
#include <cuda_fp16.h>
#include <math.h>
#include <stdint.h>

// ---------------- problem constants ----------------
#define B_      32
#define HW_     56
#define L_      3136
#define C_      384
#define NH_     12
#define HD_     32
#define WS_     7
#define NTOK_   49
#define NWIN_   64
#define BN_     2048
#define MTOT_   100352
#define HID_    1536
#define QKVN_   1152
#define SHIFT_  3
#define SCALE_  0.17677669529663687f

// ---------------- scratch ----------------
__device__ __half g_win[(size_t)MTOT_ * C_];
__device__ __half g_qkv[(size_t)MTOT_ * QKVN_];
__device__ __half g_att[(size_t)MTOT_ * C_];
__device__ float  g_x1 [(size_t)MTOT_ * C_];
__device__ __half g_h2 [(size_t)MTOT_ * C_];
__device__ __half g_hid[(size_t)MTOT_ * HID_];
__device__ __half g_wh_qkv[(size_t)QKVN_ * C_];
__device__ __half g_wh_proj[(size_t)C_ * C_];
__device__ __half g_wh_fc1[(size_t)HID_ * C_];
__device__ __half g_wh_fc2[(size_t)C_ * HID_];

// ---------------- helpers ----------------
__device__ __forceinline__ void cp_async16(uint32_t saddr, const void* gptr) {
    asm volatile("cp.async.cg.shared.global [%0], [%1], 16;" :: "r"(saddr), "l"(gptr));
}
#define CP_COMMIT() asm volatile("cp.async.commit_group;" ::: "memory")
#define CP_WAIT(n)  asm volatile("cp.async.wait_group %0;" :: "n"(n) : "memory")

__device__ __forceinline__ void mma16816(float* c, const uint32_t* a, const uint32_t* b) {
    asm volatile("mma.sync.aligned.m16n8k16.row.col.f32.f16.f16.f32 "
        "{%0,%1,%2,%3}, {%4,%5,%6,%7}, {%8,%9}, {%0,%1,%2,%3};"
        : "+f"(c[0]), "+f"(c[1]), "+f"(c[2]), "+f"(c[3])
        : "r"(a[0]), "r"(a[1]), "r"(a[2]), "r"(a[3]), "r"(b[0]), "r"(b[1]));
}

// ---------------- row map ----------------
__device__ __forceinline__ int win_row_to_orig(int r) {
    int bn = r / NTOK_, n = r - bn * NTOK_;
    int b  = bn >> 6,  wi = bn & 63;
    int i = n / WS_, j = n - i * WS_;
    int h = (wi >> 3) * WS_ + i + SHIFT_; if (h >= HW_) h -= HW_;
    int w = (wi & 7)  * WS_ + j + SHIFT_; if (w >= HW_) w -= HW_;
    return b * L_ + h * HW_ + w;
}

// ---------------- LayerNorm (half output) ----------------
template<bool SHIFT_WINDOW>
__global__ __launch_bounds__(128) void ln_kernel(const float* __restrict__ x,
                                                 const float* __restrict__ g,
                                                 const float* __restrict__ b,
                                                 __half* __restrict__ out)
{
    int r = blockIdx.x;
    int src_row = SHIFT_WINDOW ? win_row_to_orig(r) : r;
    const float* src = x + (size_t)src_row * C_;
    int t = threadIdx.x;
    float v[3], s = 0.f, s2 = 0.f;
#pragma unroll
    for (int l = 0; l < 3; ++l) { v[l] = src[t + l * 128]; s += v[l]; s2 += v[l] * v[l]; }
    __shared__ float red[8];
#pragma unroll
    for (int o = 16; o > 0; o >>= 1) {
        s  += __shfl_down_sync(0xffffffffu, s,  o);
        s2 += __shfl_down_sync(0xffffffffu, s2, o);
    }
    int lane = t & 31, wid = t >> 5;
    if (lane == 0) { red[wid] = s; red[4 + wid] = s2; }
    __syncthreads();
    s  = red[0] + red[1] + red[2] + red[3];
    s2 = red[4] + red[5] + red[6] + red[7];
    float mean = s * (1.f / C_);
    float var  = s2 * (1.f / C_) - mean * mean;
    float inv  = rsqrtf(var + 1e-5f);
    __half* dst = out + (size_t)r * C_;
#pragma unroll
    for (int l = 0; l < 3; ++l) {
        int c = t + l * 128;
        dst[c] = __float2half((v[l] - mean) * inv * g[c] + b[c]);
    }
}

// ---------------- merged weight transpose+convert (all 4 weights, one launch) -------------
// tiles: qkv 432 (36x12 of [K=384,N=1152]) ; proj 144 (12x12) ; fc1 576 (48x12) ; fc2 576 (12x48)
__global__ __launch_bounds__(256) void transpose_all(const float* __restrict__ qkv_w,
                                                     const float* __restrict__ proj_w,
                                                     const float* __restrict__ fc1_w,
                                                     const float* __restrict__ fc2_w,
                                                     __half* __restrict__ d_qkv,
                                                     __half* __restrict__ d_proj,
                                                     __half* __restrict__ d_fc1,
                                                     __half* __restrict__ d_fc2)
{
    int tb = blockIdx.x;
    const float* src; __half* dst; int K, N, tx_, ty_;
    if (tb < 432)        { src = qkv_w;  dst = d_qkv;  K = C_;   N = QKVN_; tb -= 0;    tx_ = tb % 36; ty_ = tb / 36; }
    else if (tb < 576)   { src = proj_w; dst = d_proj; K = C_;   N = C_;    tb -= 432;  tx_ = tb % 12; ty_ = tb / 12; }
    else if (tb < 1152)  { src = fc1_w;  dst = d_fc1;  K = C_;   N = HID_;  tb -= 576;  tx_ = tb % 48; ty_ = tb / 48; }
    else                 { src = fc2_w;  dst = d_fc2;  K = HID_; N = C_;    tb -= 1152; tx_ = tb % 12; ty_ = tb / 12; }

    __shared__ float t[32][33];
    int bx = tx_ * 32, by = ty_ * 32;
    int tx = threadIdx.x & 31, ty = threadIdx.x >> 5;
#pragma unroll
    for (int i = 0; i < 4; ++i)
        t[ty + i * 8][tx] = src[(size_t)(by + ty + i * 8) * N + bx + tx];
    __syncthreads();
#pragma unroll
    for (int i = 0; i < 4; ++i)
        dst[(size_t)(bx + ty + i * 8) * K + by + tx] = __float2half(t[tx][ty + i * 8]);
}

// ---------------- fp16 mma GEMM: 128x128 block, 8 warps, 4-stage 1-sync ring ----------------
// EPI: 0=+bias->half ; 1=+bias,gelu->half ; 2=+bias,win-rev+residual->float ;
//      3=+bias+residual->float
#define ASTR 40
#define ABYT (128 * ASTR * 2)
#define STGB (2 * ABYT)
#define NSTG 4
#define MM_SMEM (NSTG * STGB)

template<int EPI>
__global__ __launch_bounds__(256, 2) void mm_kernel(const __half* __restrict__ A,
                                                    const __half* __restrict__ Wt,
                                                    const float* __restrict__ bias,
                                                    const float* __restrict__ Res,
                                                    void* __restrict__ OutV,
                                                    int K, int N)
{
    extern __shared__ __half sm[];
    const int tid = threadIdx.x;
    const int w = tid >> 5, lane = tid & 31;
    const int warpM = w >> 1, warpN = w & 1;
    const int g = lane >> 2, tig = lane & 3;
    const int bx = blockIdx.x, by = blockIdx.y;

    const __half* Ab = A  + (size_t)by * 128 * K;
    const __half* Bb = Wt + (size_t)bx * 128 * K;
    uint32_t s0 = (uint32_t)__cvta_generic_to_shared(sm);

    float acc[2][8][4];
#pragma unroll
    for (int mt = 0; mt < 2; ++mt)
#pragma unroll
        for (int nt = 0; nt < 8; ++nt)
#pragma unroll
            for (int i = 0; i < 4; ++i) acc[mt][nt][i] = 0.f;

    const int KT = K >> 5;
    const int ca0 = tid, ca1 = tid + 256;

#define LOAD_STAGE(kt, st) do {                                                     \
        int _k0 = (kt) << 5;                                                        \
        uint32_t _ab = s0 + (st) * STGB;                                            \
        uint32_t _bb = _ab + ABYT;                                                  \
        { int r = ca0 >> 2, sg = ca0 & 3;                                           \
          cp_async16(_ab + (r * ASTR + sg * 8) * 2, Ab + (size_t)r * K + _k0 + sg * 8); } \
        { int r = ca1 >> 2, sg = ca1 & 3;                                           \
          cp_async16(_ab + (r * ASTR + sg * 8) * 2, Ab + (size_t)r * K + _k0 + sg * 8); } \
        { int r = ca0 >> 2, sg = ca0 & 3;                                           \
          cp_async16(_bb + (r * ASTR + sg * 8) * 2, Bb + (size_t)r * K + _k0 + sg * 8); } \
        { int r = ca1 >> 2, sg = ca1 & 3;                                           \
          cp_async16(_bb + (r * ASTR + sg * 8) * 2, Bb + (size_t)r * K + _k0 + sg * 8); } \
        CP_COMMIT();                                                                \
    } while (0)

    LOAD_STAGE(0, 0);
    LOAD_STAGE(1, 1);

    for (int kt = 0; kt < KT; ++kt) {
        int st = kt & 3;
        if (kt + 2 < KT)      { LOAD_STAGE(kt + 2, (kt + 2) & 3); CP_WAIT(2); }
        else if (kt + 1 < KT) { CP_WAIT(1); }
        else                  { CP_WAIT(0); }
        __syncthreads();

        const uint32_t* Au = (const uint32_t*)(sm + st * (STGB / 2));
        const uint32_t* Bu = Au + ABYT / 4;
#pragma unroll
        for (int s = 0; s < 2; ++s) {
            uint32_t af[2][4], bf[8][2];
            int c2 = s * 8 + tig;
#pragma unroll
            for (int mt = 0; mt < 2; ++mt) {
                int r = warpM * 32 + mt * 16 + g;
                af[mt][0] = Au[r * 20 + c2];
                af[mt][1] = Au[(r + 8) * 20 + c2];
                af[mt][2] = Au[r * 20 + c2 + 4];
                af[mt][3] = Au[(r + 8) * 20 + c2 + 4];
            }
#pragma unroll
            for (int nt = 0; nt < 8; ++nt) {
                int n = warpN * 64 + nt * 8 + g;
                bf[nt][0] = Bu[n * 20 + c2];
                bf[nt][1] = Bu[n * 20 + c2 + 4];
            }
#pragma unroll
            for (int mt = 0; mt < 2; ++mt)
#pragma unroll
                for (int nt = 0; nt < 8; ++nt)
                    mma16816(acc[mt][nt], af[mt], bf[nt]);
        }
    }

#pragma unroll
    for (int mt = 0; mt < 2; ++mt) {
#pragma unroll
        for (int rr = 0; rr < 2; ++rr) {
            int row = by * 128 + warpM * 32 + mt * 16 + g + rr * 8;
            if (EPI == 2) {
                int orow = win_row_to_orig(row);
                float* dst = (float*)OutV + (size_t)orow * C_;
                const float* rs = Res + (size_t)orow * C_;
#pragma unroll
                for (int nt = 0; nt < 8; ++nt) {
                    int c = bx * 128 + warpN * 64 + nt * 8 + tig * 2;
                    dst[c]     = acc[mt][nt][rr * 2]     + bias[c]     + rs[c];
                    dst[c + 1] = acc[mt][nt][rr * 2 + 1] + bias[c + 1] + rs[c + 1];
                }
            } else if (EPI == 0 || EPI == 1) {
                __half* dst = (__half*)OutV + (size_t)row * N;
#pragma unroll
                for (int nt = 0; nt < 8; ++nt) {
                    int c = bx * 128 + warpN * 64 + nt * 8 + tig * 2;
                    float v0 = acc[mt][nt][rr * 2]     + bias[c];
                    float v1 = acc[mt][nt][rr * 2 + 1] + bias[c + 1];
                    if (EPI == 1) {
                        v0 = 0.5f * v0 * (1.f + erff(v0 * 0.70710678118654752f));
                        v1 = 0.5f * v1 * (1.f + erff(v1 * 0.70710678118654752f));
                    }
                    *(__half2*)(dst + c) = __halves2half2(__float2half(v0), __float2half(v1));
                }
            } else {
                float* dst = (float*)OutV + (size_t)row * N;
#pragma unroll
                for (int nt = 0; nt < 8; ++nt) {
                    int c = bx * 128 + warpN * 64 + nt * 8 + tig * 2;
                    float v0 = acc[mt][nt][rr * 2]     + bias[c]     + Res[(size_t)row * N + c];
                    float v1 = acc[mt][nt][rr * 2 + 1] + bias[c + 1] + Res[(size_t)row * N + c + 1];
                    dst[c] = v0; dst[c + 1] = v1;
                }
            }
        }
    }
}

// ---------------- Attention (half2-vectorized loads) ----------------
__global__ __launch_bounds__(128) void attn_kernel(const float* __restrict__ rpb,
                                                   const float* __restrict__ mask)
{
    int bh = blockIdx.x;
    int bn = bh / NH_, head = bh - bn * NH_;
    int t = threadIdx.x;

    __shared__ float q [NTOK_][HD_];
    __shared__ float kk[NTOK_][HD_];
    __shared__ float vv[NTOK_][HD_];
    __shared__ float s [NTOK_][52];

    const __half* base = g_qkv + (size_t)bn * NTOK_ * QKVN_ + head * HD_;
    for (int idx = t; idx < NTOK_ * (HD_ / 2); idx += 128) {
        int n = idx >> 4, d2 = idx & 15;
        const __half2* p = (const __half2*)(base + (size_t)n * QKVN_) + d2;
        float2 qv = __half22float2(p[0]);
        float2 kv = __half22float2(p[C_ / 2]);
        float2 vV = __half22float2(p[C_]);
        q [n][2 * d2]     = qv.x * SCALE_;
        q [n][2 * d2 + 1] = qv.y * SCALE_;
        kk[n][2 * d2]     = kv.x;
        kk[n][2 * d2 + 1] = kv.y;
        vv[n][2 * d2]     = vV.x;
        vv[n][2 * d2 + 1] = vV.y;
    }
    __syncthreads();

    int wi = bn & 63;
    const float* mrow = mask + (size_t)wi * NTOK_ * NTOK_;
    for (int idx = t; idx < NTOK_ * NTOK_; idx += 128) {
        int n = idx / NTOK_, m = idx - n * NTOK_;
        float acc = 0.f;
#pragma unroll
        for (int d = 0; d < HD_; ++d) acc = fmaf(q[n][d], kk[m][d], acc);
        int di = n / WS_ - m / WS_ + WS_ - 1;
        int dj = n % WS_ - m % WS_ + WS_ - 1;
        acc += rpb[(di * (2 * WS_ - 1) + dj) * NH_ + head] + mrow[idx];
        s[n][m] = acc;
    }
    __syncthreads();

    if (t < NTOK_) {
        float mx = -1e30f;
#pragma unroll 7
        for (int m = 0; m < NTOK_; ++m) mx = fmaxf(mx, s[t][m]);
        float sum = 0.f;
#pragma unroll 7
        for (int m = 0; m < NTOK_; ++m) { float e = __expf(s[t][m] - mx); s[t][m] = e; sum += e; }
        float inv = 1.f / sum;
#pragma unroll 7
        for (int m = 0; m < NTOK_; ++m) s[t][m] *= inv;
    }
    __syncthreads();

    for (int idx = t; idx < NTOK_ * HD_; idx += 128) {
        int n = idx >> 5, d = idx & 31;
        float acc = 0.f;
#pragma unroll 7
        for (int m = 0; m < NTOK_; ++m) acc = fmaf(s[n][m], vv[m][d], acc);
        g_att[((size_t)bn * NTOK_ + n) * C_ + head * HD_ + d] = __float2half(acc);
    }
}

// ---------------- launch ----------------
extern "C" void kernel_launch(void* const* d_in, const int* in_sizes, int n_in,
                              void* d_out, int out_size)
{
    const float* x       = (const float*)d_in[0];
    const float* mask    = (const float*)d_in[1];
    const float* n1g     = (const float*)d_in[2];
    const float* n1b     = (const float*)d_in[3];
    const float* qkv_w   = (const float*)d_in[4];
    const float* qkv_b   = (const float*)d_in[5];
    const float* rpb     = (const float*)d_in[6];
    const float* proj_w  = (const float*)d_in[7];
    const float* proj_b  = (const float*)d_in[8];
    const float* n2g     = (const float*)d_in[9];
    const float* n2b     = (const float*)d_in[10];
    const float* fc1_w   = (const float*)d_in[11];
    const float* fc1_b   = (const float*)d_in[12];
    const float* fc2_w   = (const float*)d_in[13];
    const float* fc2_b   = (const float*)d_in[14];
    float* out = (float*)d_out;

    __half *p_win, *p_qkv, *p_att, *p_h2, *p_hid;
    float  *p_x1;
    __half *pW_qkv, *pW_proj, *pW_fc1, *pW_fc2;
    cudaGetSymbolAddress((void**)&p_win, g_win);
    cudaGetSymbolAddress((void**)&p_qkv, g_qkv);
    cudaGetSymbolAddress((void**)&p_att, g_att);
    cudaGetSymbolAddress((void**)&p_x1,  g_x1);
    cudaGetSymbolAddress((void**)&p_h2,  g_h2);
    cudaGetSymbolAddress((void**)&p_hid, g_hid);
    cudaGetSymbolAddress((void**)&pW_qkv,  g_wh_qkv);
    cudaGetSymbolAddress((void**)&pW_proj, g_wh_proj);
    cudaGetSymbolAddress((void**)&pW_fc1,  g_wh_fc1);
    cudaGetSymbolAddress((void**)&pW_fc2,  g_wh_fc2);

    cudaFuncSetAttribute(mm_kernel<0>, cudaFuncAttributeMaxDynamicSharedMemorySize, MM_SMEM);
    cudaFuncSetAttribute(mm_kernel<1>, cudaFuncAttributeMaxDynamicSharedMemorySize, MM_SMEM);
    cudaFuncSetAttribute(mm_kernel<2>, cudaFuncAttributeMaxDynamicSharedMemorySize, MM_SMEM);
    cudaFuncSetAttribute(mm_kernel<3>, cudaFuncAttributeMaxDynamicSharedMemorySize, MM_SMEM);

    // 0) transpose + fp16-convert all weights -> [N,K] (single launch, 1728 tiles)
    transpose_all<<<1728, 256>>>(qkv_w, proj_w, fc1_w, fc2_w,
                                 pW_qkv, pW_proj, pW_fc1, pW_fc2);

    // 1) LN1 + roll + window partition (half)
    ln_kernel<true><<<MTOT_, 128>>>(x, n1g, n1b, p_win);

    // 2) QKV GEMM -> half
    mm_kernel<0><<<dim3(QKVN_ / 128, MTOT_ / 128), 256, MM_SMEM>>>(p_win, pW_qkv, qkv_b, nullptr,
                                                                   p_qkv, C_, QKVN_);
    // 3) windowed attention -> half
    attn_kernel<<<BN_ * NH_, 128>>>(rpb, mask);

    // 4) proj + window reverse + residual -> float (orig order)
    mm_kernel<2><<<dim3(C_ / 128, MTOT_ / 128), 256, MM_SMEM>>>(p_att, pW_proj, proj_b, x,
                                                                p_x1, C_, C_);
    // 5) LN2 -> half
    ln_kernel<false><<<MTOT_, 128>>>(p_x1, n2g, n2b, p_h2);

    // 6) fc1 + GELU -> half
    mm_kernel<1><<<dim3(HID_ / 128, MTOT_ / 128), 256, MM_SMEM>>>(p_h2, pW_fc1, fc1_b, nullptr,
                                                                  p_hid, C_, HID_);
    // 7) fc2 + residual -> out (float)
    mm_kernel<3><<<dim3(C_ / 128, MTOT_ / 128), 256, MM_SMEM>>>(p_hid, pW_fc2, fc2_b, p_x1,
                                                                out, HID_, C_);
}

// round 14
// speedup vs baseline: 1.4639x; 1.4512x over previous
#include <cuda_runtime.h>
#include <cuda_fp16.h>
#include <math.h>
#include <stdint.h>

// ---------------- problem constants ----------------
#define B_      32
#define HW_     56
#define L_      3136
#define C_      384
#define NH_     12
#define HD_     32
#define WS_     7
#define NTOK_   49
#define NWIN_   64
#define BN_     2048
#define MTOT_   100352
#define HID_    1536
#define QKVN_   1152
#define SHIFT_  3
#define SCALE_  0.17677669529663687f

// ---------------- scratch ----------------
__device__ __half g_win[(size_t)MTOT_ * C_];
__device__ __half g_qkv[(size_t)MTOT_ * QKVN_];
__device__ __half g_att[(size_t)MTOT_ * C_];
__device__ float  g_x1 [(size_t)MTOT_ * C_];
__device__ __half g_h2 [(size_t)MTOT_ * C_];
__device__ __half g_hid[(size_t)MTOT_ * HID_];
__device__ __half g_wh_qkv[(size_t)QKVN_ * C_];
__device__ __half g_wh_proj[(size_t)C_ * C_];
__device__ __half g_wh_fc1[(size_t)HID_ * C_];
__device__ __half g_wh_fc2[(size_t)C_ * HID_];

// ---------------- helpers ----------------
__device__ __forceinline__ void cp_async16(uint32_t saddr, const void* gptr) {
    asm volatile("cp.async.cg.shared.global [%0], [%1], 16;" :: "r"(saddr), "l"(gptr));
}
#define CP_COMMIT() asm volatile("cp.async.commit_group;" ::: "memory")
#define CP_WAIT(n)  asm volatile("cp.async.wait_group %0;" :: "n"(n) : "memory")

__device__ __forceinline__ void mma16816(float* c, const uint32_t* a, const uint32_t* b) {
    asm volatile("mma.sync.aligned.m16n8k16.row.col.f32.f16.f16.f32 "
        "{%0,%1,%2,%3}, {%4,%5,%6,%7}, {%8,%9}, {%0,%1,%2,%3};"
        : "+f"(c[0]), "+f"(c[1]), "+f"(c[2]), "+f"(c[3])
        : "r"(a[0]), "r"(a[1]), "r"(a[2]), "r"(a[3]), "r"(b[0]), "r"(b[1]));
}

// ---------------- row map ----------------
__device__ __forceinline__ int win_row_to_orig(int r) {
    int bn = r / NTOK_, n = r - bn * NTOK_;
    int b  = bn >> 6,  wi = bn & 63;
    int i = n / WS_, j = n - i * WS_;
    int h = (wi >> 3) * WS_ + i + SHIFT_; if (h >= HW_) h -= HW_;
    int w = (wi & 7)  * WS_ + j + SHIFT_; if (w >= HW_) w -= HW_;
    return b * L_ + h * HW_ + w;
}

// ---------------- LayerNorm (half output) ----------------
template<bool SHIFT_WINDOW>
__global__ __launch_bounds__(128) void ln_kernel(const float* __restrict__ x,
                                                 const float* __restrict__ g,
                                                 const float* __restrict__ b,
                                                 __half* __restrict__ out)
{
    int r = blockIdx.x;
    int src_row = SHIFT_WINDOW ? win_row_to_orig(r) : r;
    const float* src = x + (size_t)src_row * C_;
    int t = threadIdx.x;
    float v[3], s = 0.f, s2 = 0.f;
#pragma unroll
    for (int l = 0; l < 3; ++l) { v[l] = src[t + l * 128]; s += v[l]; s2 += v[l] * v[l]; }
    __shared__ float red[8];
#pragma unroll
    for (int o = 16; o > 0; o >>= 1) {
        s  += __shfl_down_sync(0xffffffffu, s,  o);
        s2 += __shfl_down_sync(0xffffffffu, s2, o);
    }
    int lane = t & 31, wid = t >> 5;
    if (lane == 0) { red[wid] = s; red[4 + wid] = s2; }
    __syncthreads();
    s  = red[0] + red[1] + red[2] + red[3];
    s2 = red[4] + red[5] + red[6] + red[7];
    float mean = s * (1.f / C_);
    float var  = s2 * (1.f / C_) - mean * mean;
    float inv  = rsqrtf(var + 1e-5f);
    __half* dst = out + (size_t)r * C_;
#pragma unroll
    for (int l = 0; l < 3; ++l) {
        int c = t + l * 128;
        dst[c] = __float2half((v[l] - mean) * inv * g[c] + b[c]);
    }
}

// ---------------- merged weight transpose+convert (all 4 weights, one launch) -------------
__global__ __launch_bounds__(256) void transpose_all(const float* __restrict__ qkv_w,
                                                     const float* __restrict__ proj_w,
                                                     const float* __restrict__ fc1_w,
                                                     const float* __restrict__ fc2_w,
                                                     __half* __restrict__ d_qkv,
                                                     __half* __restrict__ d_proj,
                                                     __half* __restrict__ d_fc1,
                                                     __half* __restrict__ d_fc2)
{
    int tb = blockIdx.x;
    const float* src; __half* dst; int K, N, tx_, ty_;
    if (tb < 432)        { src = qkv_w;  dst = d_qkv;  K = C_;   N = QKVN_; tb -= 0;    tx_ = tb % 36; ty_ = tb / 36; }
    else if (tb < 576)   { src = proj_w; dst = d_proj; K = C_;   N = C_;    tb -= 432;  tx_ = tb % 12; ty_ = tb / 12; }
    else if (tb < 1152)  { src = fc1_w;  dst = d_fc1;  K = C_;   N = HID_;  tb -= 576;  tx_ = tb % 48; ty_ = tb / 48; }
    else                 { src = fc2_w;  dst = d_fc2;  K = HID_; N = C_;    tb -= 1152; tx_ = tb % 12; ty_ = tb / 12; }

    __shared__ float t[32][33];
    int bx = tx_ * 32, by = ty_ * 32;
    int tx = threadIdx.x & 31, ty = threadIdx.x >> 5;
#pragma unroll
    for (int i = 0; i < 4; ++i)
        t[ty + i * 8][tx] = src[(size_t)(by + ty + i * 8) * N + bx + tx];
    __syncthreads();
#pragma unroll
    for (int i = 0; i < 4; ++i)
        dst[(size_t)(bx + ty + i * 8) * K + by + tx] = __float2half(t[tx][ty + i * 8]);
}

// ---------------- fp16 mma GEMM: 128x128 block, 8 warps, 4-stage 1-sync ring ----------------
#define ASTR 40
#define ABYT (128 * ASTR * 2)
#define STGB (2 * ABYT)
#define NSTG 4
#define MM_SMEM (NSTG * STGB)

template<int EPI>
__global__ __launch_bounds__(256, 2) void mm_kernel(const __half* __restrict__ A,
                                                    const __half* __restrict__ Wt,
                                                    const float* __restrict__ bias,
                                                    const float* __restrict__ Res,
                                                    void* __restrict__ OutV,
                                                    int K, int N)
{
    extern __shared__ __half sm[];
    const int tid = threadIdx.x;
    const int w = tid >> 5, lane = tid & 31;
    const int warpM = w >> 1, warpN = w & 1;
    const int g = lane >> 2, tig = lane & 3;
    const int bx = blockIdx.x, by = blockIdx.y;

    const __half* Ab = A  + (size_t)by * 128 * K;
    const __half* Bb = Wt + (size_t)bx * 128 * K;
    uint32_t s0 = (uint32_t)__cvta_generic_to_shared(sm);

    float acc[2][8][4];
#pragma unroll
    for (int mt = 0; mt < 2; ++mt)
#pragma unroll
        for (int nt = 0; nt < 8; ++nt)
#pragma unroll
            for (int i = 0; i < 4; ++i) acc[mt][nt][i] = 0.f;

    const int KT = K >> 5;
    const int ca0 = tid, ca1 = tid + 256;

#define LOAD_STAGE(kt, st) do {                                                     \
        int _k0 = (kt) << 5;                                                        \
        uint32_t _ab = s0 + (st) * STGB;                                            \
        uint32_t _bb = _ab + ABYT;                                                  \
        { int r = ca0 >> 2, sg = ca0 & 3;                                           \
          cp_async16(_ab + (r * ASTR + sg * 8) * 2, Ab + (size_t)r * K + _k0 + sg * 8); } \
        { int r = ca1 >> 2, sg = ca1 & 3;                                           \
          cp_async16(_ab + (r * ASTR + sg * 8) * 2, Ab + (size_t)r * K + _k0 + sg * 8); } \
        { int r = ca0 >> 2, sg = ca0 & 3;                                           \
          cp_async16(_bb + (r * ASTR + sg * 8) * 2, Bb + (size_t)r * K + _k0 + sg * 8); } \
        { int r = ca1 >> 2, sg = ca1 & 3;                                           \
          cp_async16(_bb + (r * ASTR + sg * 8) * 2, Bb + (size_t)r * K + _k0 + sg * 8); } \
        CP_COMMIT();                                                                \
    } while (0)

    LOAD_STAGE(0, 0);
    LOAD_STAGE(1, 1);

    for (int kt = 0; kt < KT; ++kt) {
        int st = kt & 3;
        if (kt + 2 < KT)      { LOAD_STAGE(kt + 2, (kt + 2) & 3); CP_WAIT(2); }
        else if (kt + 1 < KT) { CP_WAIT(1); }
        else                  { CP_WAIT(0); }
        __syncthreads();

        const uint32_t* Au = (const uint32_t*)(sm + st * (STGB / 2));
        const uint32_t* Bu = Au + ABYT / 4;
#pragma unroll
        for (int s = 0; s < 2; ++s) {
            uint32_t af[2][4], bf[8][2];
            int c2 = s * 8 + tig;
#pragma unroll
            for (int mt = 0; mt < 2; ++mt) {
                int r = warpM * 32 + mt * 16 + g;
                af[mt][0] = Au[r * 20 + c2];
                af[mt][1] = Au[(r + 8) * 20 + c2];
                af[mt][2] = Au[r * 20 + c2 + 4];
                af[mt][3] = Au[(r + 8) * 20 + c2 + 4];
            }
#pragma unroll
            for (int nt = 0; nt < 8; ++nt) {
                int n = warpN * 64 + nt * 8 + g;
                bf[nt][0] = Bu[n * 20 + c2];
                bf[nt][1] = Bu[n * 20 + c2 + 4];
            }
#pragma unroll
            for (int mt = 0; mt < 2; ++mt)
#pragma unroll
                for (int nt = 0; nt < 8; ++nt)
                    mma16816(acc[mt][nt], af[mt], bf[nt]);
        }
    }

#pragma unroll
    for (int mt = 0; mt < 2; ++mt) {
#pragma unroll
        for (int rr = 0; rr < 2; ++rr) {
            int row = by * 128 + warpM * 32 + mt * 16 + g + rr * 8;
            if (EPI == 2) {
                int orow = win_row_to_orig(row);
                float* dst = (float*)OutV + (size_t)orow * C_;
                const float* rs = Res + (size_t)orow * C_;
#pragma unroll
                for (int nt = 0; nt < 8; ++nt) {
                    int c = bx * 128 + warpN * 64 + nt * 8 + tig * 2;
                    dst[c]     = acc[mt][nt][rr * 2]     + bias[c]     + rs[c];
                    dst[c + 1] = acc[mt][nt][rr * 2 + 1] + bias[c + 1] + rs[c + 1];
                }
            } else if (EPI == 0 || EPI == 1) {
                __half* dst = (__half*)OutV + (size_t)row * N;
#pragma unroll
                for (int nt = 0; nt < 8; ++nt) {
                    int c = bx * 128 + warpN * 64 + nt * 8 + tig * 2;
                    float v0 = acc[mt][nt][rr * 2]     + bias[c];
                    float v1 = acc[mt][nt][rr * 2 + 1] + bias[c + 1];
                    if (EPI == 1) {
                        v0 = 0.5f * v0 * (1.f + erff(v0 * 0.70710678118654752f));
                        v1 = 0.5f * v1 * (1.f + erff(v1 * 0.70710678118654752f));
                    }
                    *(__half2*)(dst + c) = __halves2half2(__float2half(v0), __float2half(v1));
                }
            } else {
                float* dst = (float*)OutV + (size_t)row * N;
#pragma unroll
                for (int nt = 0; nt < 8; ++nt) {
                    int c = bx * 128 + warpN * 64 + nt * 8 + tig * 2;
                    float v0 = acc[mt][nt][rr * 2]     + bias[c]     + Res[(size_t)row * N + c];
                    float v1 = acc[mt][nt][rr * 2 + 1] + bias[c + 1] + Res[(size_t)row * N + c + 1];
                    dst[c] = v0; dst[c + 1] = v1;
                }
            }
        }
    }
}

// ---------------- Attention (K stored transposed: conflict-free QK^T) ----------------
__global__ __launch_bounds__(128) void attn_kernel(const float* __restrict__ rpb,
                                                   const float* __restrict__ mask)
{
    int bh = blockIdx.x;
    int bn = bh / NH_, head = bh - bn * NH_;
    int t = threadIdx.x;

    __shared__ float q  [NTOK_][HD_];
    __shared__ float kkT[HD_][52];     // transposed K: kkT[d][m]
    __shared__ float vv [NTOK_][HD_];
    __shared__ float s  [NTOK_][52];

    const __half* base = g_qkv + (size_t)bn * NTOK_ * QKVN_ + head * HD_;
    for (int idx = t; idx < NTOK_ * (HD_ / 2); idx += 128) {
        int n = idx >> 4, d2 = idx & 15;
        const __half2* p = (const __half2*)(base + (size_t)n * QKVN_) + d2;
        float2 qv = __half22float2(p[0]);
        float2 kv = __half22float2(p[C_ / 2]);
        float2 vV = __half22float2(p[C_]);
        q [n][2 * d2]     = qv.x * SCALE_;
        q [n][2 * d2 + 1] = qv.y * SCALE_;
        kkT[2 * d2][n]     = kv.x;
        kkT[2 * d2 + 1][n] = kv.y;
        vv[n][2 * d2]     = vV.x;
        vv[n][2 * d2 + 1] = vV.y;
    }
    __syncthreads();

    int wi = bn & 63;
    const float* mrow = mask + (size_t)wi * NTOK_ * NTOK_;
    for (int idx = t; idx < NTOK_ * NTOK_; idx += 128) {
        int n = idx / NTOK_, m = idx - n * NTOK_;
        float acc = 0.f;
#pragma unroll
        for (int d = 0; d < HD_; ++d) acc = fmaf(q[n][d], kkT[d][m], acc);
        int di = n / WS_ - m / WS_ + WS_ - 1;
        int dj = n % WS_ - m % WS_ + WS_ - 1;
        acc += rpb[(di * (2 * WS_ - 1) + dj) * NH_ + head] + mrow[idx];
        s[n][m] = acc;
    }
    __syncthreads();

    if (t < NTOK_) {
        float mx = -1e30f;
#pragma unroll 7
        for (int m = 0; m < NTOK_; ++m) mx = fmaxf(mx, s[t][m]);
        float sum = 0.f;
#pragma unroll 7
        for (int m = 0; m < NTOK_; ++m) { float e = __expf(s[t][m] - mx); s[t][m] = e; sum += e; }
        float inv = 1.f / sum;
#pragma unroll 7
        for (int m = 0; m < NTOK_; ++m) s[t][m] *= inv;
    }
    __syncthreads();

    for (int idx = t; idx < NTOK_ * HD_; idx += 128) {
        int n = idx >> 5, d = idx & 31;
        float acc = 0.f;
#pragma unroll 7
        for (int m = 0; m < NTOK_; ++m) acc = fmaf(s[n][m], vv[m][d], acc);
        g_att[((size_t)bn * NTOK_ + n) * C_ + head * HD_ + d] = __float2half(acc);
    }
}

// ---------------- launch ----------------
extern "C" void kernel_launch(void* const* d_in, const int* in_sizes, int n_in,
                              void* d_out, int out_size)
{
    const float* x       = (const float*)d_in[0];
    const float* mask    = (const float*)d_in[1];
    const float* n1g     = (const float*)d_in[2];
    const float* n1b     = (const float*)d_in[3];
    const float* qkv_w   = (const float*)d_in[4];
    const float* qkv_b   = (const float*)d_in[5];
    const float* rpb     = (const float*)d_in[6];
    const float* proj_w  = (const float*)d_in[7];
    const float* proj_b  = (const float*)d_in[8];
    const float* n2g     = (const float*)d_in[9];
    const float* n2b     = (const float*)d_in[10];
    const float* fc1_w   = (const float*)d_in[11];
    const float* fc1_b   = (const float*)d_in[12];
    const float* fc2_w   = (const float*)d_in[13];
    const float* fc2_b   = (const float*)d_in[14];
    float* out = (float*)d_out;

    __half *p_win, *p_qkv, *p_att, *p_h2, *p_hid;
    float  *p_x1;
    __half *pW_qkv, *pW_proj, *pW_fc1, *pW_fc2;
    cudaGetSymbolAddress((void**)&p_win, g_win);
    cudaGetSymbolAddress((void**)&p_qkv, g_qkv);
    cudaGetSymbolAddress((void**)&p_att, g_att);
    cudaGetSymbolAddress((void**)&p_x1,  g_x1);
    cudaGetSymbolAddress((void**)&p_h2,  g_h2);
    cudaGetSymbolAddress((void**)&p_hid, g_hid);
    cudaGetSymbolAddress((void**)&pW_qkv,  g_wh_qkv);
    cudaGetSymbolAddress((void**)&pW_proj, g_wh_proj);
    cudaGetSymbolAddress((void**)&pW_fc1,  g_wh_fc1);
    cudaGetSymbolAddress((void**)&pW_fc2,  g_wh_fc2);

    cudaFuncSetAttribute(mm_kernel<0>, cudaFuncAttributeMaxDynamicSharedMemorySize, MM_SMEM);
    cudaFuncSetAttribute(mm_kernel<1>, cudaFuncAttributeMaxDynamicSharedMemorySize, MM_SMEM);
    cudaFuncSetAttribute(mm_kernel<2>, cudaFuncAttributeMaxDynamicSharedMemorySize, MM_SMEM);
    cudaFuncSetAttribute(mm_kernel<3>, cudaFuncAttributeMaxDynamicSharedMemorySize, MM_SMEM);

    // 0) transpose + fp16-convert all weights -> [N,K] (single launch, 1728 tiles)
    transpose_all<<<1728, 256>>>(qkv_w, proj_w, fc1_w, fc2_w,
                                 pW_qkv, pW_proj, pW_fc1, pW_fc2);

    // 1) LN1 + roll + window partition (half)
    ln_kernel<true><<<MTOT_, 128>>>(x, n1g, n1b, p_win);

    // 2) QKV GEMM -> half
    mm_kernel<0><<<dim3(QKVN_ / 128, MTOT_ / 128), 256, MM_SMEM>>>(p_win, pW_qkv, qkv_b, nullptr,
                                                                   p_qkv, C_, QKVN_);
    // 3) windowed attention -> half
    attn_kernel<<<BN_ * NH_, 128>>>(rpb, mask);

    // 4) proj + window reverse + residual -> float (orig order)
    mm_kernel<2><<<dim3(C_ / 128, MTOT_ / 128), 256, MM_SMEM>>>(p_att, pW_proj, proj_b, x,
                                                                p_x1, C_, C_);
    // 5) LN2 -> half
    ln_kernel<false><<<MTOT_, 128>>>(p_x1, n2g, n2b, p_h2);

    // 6) fc1 + GELU -> half
    mm_kernel<1><<<dim3(HID_ / 128, MTOT_ / 128), 256, MM_SMEM>>>(p_h2, pW_fc1, fc1_b, nullptr,
                                                                  p_hid, C_, HID_);
    // 7) fc2 + residual -> out (float)
    mm_kernel<3><<<dim3(C_ / 128, MTOT_ / 128), 256, MM_SMEM>>>(p_hid, pW_fc2, fc2_b, p_x1,
                                                                out, HID_, C_);
}